// round 11
// baseline (speedup 1.0000x reference)
#include <cuda_runtime.h>

// LoCon1d: out[b][o][s] = bias[o][s] + sum_{c,k} in[b][c][s+k-1] * w[o][c][s][k]
// input (16,64,1024), weight (64,64,1024,3), bias (64,1024), out (16,64,1024), all f32.
//
// CTA: 8-wide s-tile, all 64 couts, all 16 batches, full c-reduction.
// Input tile transposed into smem [c][j][b] (j = s-1 .. s+8, swizzled groups).
// Thread = (o, s-quad, batch-half): weights are 3 contiguous LDG.128 per c,
// input rows are broadcast-heavy LDS.128, math is packed fp32x2 FMA.

#define CIN   64
#define COUT  64
#define SLEN  1024
#define BATCH 16
#define SP    8
#define JROWS 10
#define TPB   256

typedef unsigned long long ull;

__device__ __forceinline__ ull pack2(float w) {
    ull r; asm("mov.b64 %0, {%1, %1};" : "=l"(r) : "f"(w)); return r;
}
__device__ __forceinline__ void fma2(ull& a, ull x, ull w) {
    asm("fma.rn.f32x2 %0, %1, %2, %0;" : "+l"(a) : "l"(x), "l"(w));
}
__device__ __forceinline__ float2 unpack2(ull a) {
    float2 f; asm("mov.b64 {%0, %1}, %2;" : "=f"(f.x), "=f"(f.y) : "l"(a)); return f;
}

__global__ __launch_bounds__(TPB)
void locon_kernel(const float* __restrict__ input,
                  const float* __restrict__ weight,
                  const float* __restrict__ bias,
                  float* __restrict__ out)
{
    __shared__ float sm[CIN * JROWS * BATCH];   // 40960 B
    const int s0  = blockIdx.x * SP;
    const int tid = threadIdx.x;

    // ---- fill: transpose input tile into smem (coalesced float4 along s) ----
    // task t = it*TPB + tid: chunk = t&3 (s-subrange), row = t>>2 -> (b, c)
    // chunk covers gs = s0-4+4*chunk + e ; smem row j = gs - s0 + 1 = 4*chunk-3+e
#pragma unroll
    for (int it = 0; it < 16; it++) {
        const int chunk = tid & 3;                    // constant per thread
        const int row   = it * (TPB / 4) + (tid >> 2);
        const int b = row & 15, c = row >> 4;
        const int bg = b >> 2, bsub = b & 3;
        const float* gin = input + ((size_t)b * CIN + c) * SLEN;
        if (chunk == 1 || chunk == 2) {
            const float4 v = *(const float4*)(gin + s0 - 4 + chunk * 4);
            const float vv[4] = { v.x, v.y, v.z, v.w };
#pragma unroll
            for (int e = 0; e < 4; e++) {
                const int j = chunk * 4 - 3 + e;      // 1..4 or 5..8
                const int slot = ((bg + (j >> 1)) & 3) * 4 + bsub;
                sm[(c * JROWS + j) * BATCH + slot] = vv[e];
            }
        } else if (chunk == 0) {                      // j = 0, gs = s0-1
            const int gs = s0 - 1;
            const float v = (gs >= 0) ? gin[gs] : 0.0f;
            sm[(c * JROWS + 0) * BATCH + (bg & 3) * 4 + bsub] = v;
        } else {                                      // chunk 3: j = 9, gs = s0+8
            const int gs = s0 + 8;
            const float v = (gs < SLEN) ? gin[gs] : 0.0f;
            // j=9 -> j>>1 = 4 -> (bg+4)&3 = bg
            sm[(c * JROWS + 9) * BATCH + (bg & 3) * 4 + bsub] = v;
        }
    }
    __syncthreads();

    // ---- compute: thread = (o, squad, bhalf) ----
    const int o  = tid >> 2;
    const int sq = (tid >> 1) & 1;
    const int bh = tid & 1;
    const int sg = s0 + 4 * sq;        // global s base of this thread's quad
    const int g0 = 2 * bh;             // first b-group (of 4 floats)
    const int h  = g0 + 2 * sq;        // slot pre-add: j>>1 = 2*sq + (r>>1)

    ull acc[16];                        // [si][u] : si = s in quad, u = f32x2 slot
#pragma unroll
    for (int i = 0; i < 16; i++) acc[i] = 0ULL;

    const float4* wp = (const float4*)(weight + ((size_t)o * CIN * SLEN + sg) * 3);
    float4 w0 = wp[0], w1 = wp[1], w2 = wp[2];
    wp += (SLEN * 3) / 4;

#pragma unroll 2
    for (int c = 0; c < CIN; c++) {
        float4 n0, n1, n2;
        if (c < CIN - 1) { n0 = wp[0]; n1 = wp[1]; n2 = wp[2]; }

        // W[si][k] packed to f32x2
        ull W[4][3];
        W[0][0] = pack2(w0.x); W[0][1] = pack2(w0.y); W[0][2] = pack2(w0.z);
        W[1][0] = pack2(w0.w); W[1][1] = pack2(w1.x); W[1][2] = pack2(w1.y);
        W[2][0] = pack2(w1.z); W[2][1] = pack2(w1.w); W[2][2] = pack2(w2.x);
        W[3][0] = pack2(w2.y); W[3][1] = pack2(w2.z); W[3][2] = pack2(w2.w);

        const float* base = sm + (c * JROWS + 4 * sq) * BATCH;
#pragma unroll
        for (int r = 0; r < 6; r++) {              // input row j = 4*sq + r
            const int sl0 = ((h +     (r >> 1)) & 3) * 4;
            const int sl1 = ((h + 1 + (r >> 1)) & 3) * 4;
            const float* rowp = base + r * BATCH;
            const ulonglong2 va = *(const ulonglong2*)(rowp + sl0);  // batches g0*4..+3
            const ulonglong2 vb = *(const ulonglong2*)(rowp + sl1);  // batches g0*4+4..+7
#pragma unroll
            for (int si = 0; si < 4; si++)
#pragma unroll
                for (int k = 0; k < 3; k++)
                    if (si + k == r) {
                        const ull Wv = W[si][k];
                        fma2(acc[si * 4 + 0], va.x, Wv);
                        fma2(acc[si * 4 + 1], va.y, Wv);
                        fma2(acc[si * 4 + 2], vb.x, Wv);
                        fma2(acc[si * 4 + 3], vb.y, Wv);
                    }
        }

        w0 = n0; w1 = n1; w2 = n2;
        wp += (SLEN * 3) / 4;
    }

    // ---- bias + store: float4 along s per batch row ----
    const float4 bv = *(const float4*)(bias + (size_t)o * SLEN + sg);
#pragma unroll
    for (int u = 0; u < 4; u++) {
        const float2 p0 = unpack2(acc[0 * 4 + u]);
        const float2 p1 = unpack2(acc[1 * 4 + u]);
        const float2 p2 = unpack2(acc[2 * 4 + u]);
        const float2 p3 = unpack2(acc[3 * 4 + u]);
        const int b0 = bh * 8 + u * 2;
        float4 r0 = make_float4(p0.x + bv.x, p1.x + bv.y, p2.x + bv.z, p3.x + bv.w);
        float4 r1 = make_float4(p0.y + bv.x, p1.y + bv.y, p2.y + bv.z, p3.y + bv.w);
        *(float4*)(out + ((size_t)(b0 + 0) * COUT + o) * SLEN + sg) = r0;
        *(float4*)(out + ((size_t)(b0 + 1) * COUT + o) * SLEN + sg) = r1;
    }
}

extern "C" void kernel_launch(void* const* d_in, const int* in_sizes, int n_in,
                              void* d_out, int out_size)
{
    const float* input  = (const float*)d_in[0];  // (16, 64, 1024)
    const float* weight = (const float*)d_in[1];  // (64, 64, 1024, 3)
    const float* bias   = (const float*)d_in[2];  // (64, 1024)
    float* out = (float*)d_out;                   // (16, 64, 1024)

    locon_kernel<<<SLEN / SP, TPB>>>(input, weight, bias, out);  // 128 CTAs x 256
}